// round 4
// baseline (speedup 1.0000x reference)
#include <cuda_runtime.h>
#include <cstdint>
#include <cstddef>

// Problem constants
#define T_STEPS 2048
#define BATCH   16
#define DIM     1024
#define NDIM    64
#define PROJ    256            // 4 * NDIM (k, v, q, a)
#define PSTRIDE 4096           // floats per time step = BATCH * PROJ
#define LOG2E   1.44269504f

typedef unsigned long long u64;

// Scratch: projections P[(t*BATCH + b)*256 + c], c = {k:0..63, v:64..127, q:128..191, a:192..255}
__device__ float g_P[(size_t)T_STEPS * BATCH * PROJ];   // 33.5 MB

// ---------------------------------------------------------------------------
// packed f32x2 helpers (sm_103a FFMA2 path — ptxas never emits these from C++)
// ---------------------------------------------------------------------------
__device__ __forceinline__ u64 pack2(float lo, float hi) {
    u64 r; asm("mov.b64 %0, {%1, %2};" : "=l"(r) : "f"(lo), "f"(hi)); return r;
}
__device__ __forceinline__ void unpack2(float& lo, float& hi, u64 x) {
    asm("mov.b64 {%0, %1}, %2;" : "=f"(lo), "=f"(hi) : "l"(x));
}
__device__ __forceinline__ u64 fma2(u64 a, u64 b, u64 c) {
    u64 d; asm("fma.rn.f32x2 %0, %1, %2, %3;" : "=l"(d) : "l"(a), "l"(b), "l"(c)); return d;
}
__device__ __forceinline__ u64 mul2(u64 a, u64 b) {
    u64 d; asm("mul.rn.f32x2 %0, %1, %2;" : "=l"(d) : "l"(a), "l"(b)); return d;
}

__device__ __forceinline__ float sigmoid_neg_l2(float z2)  // z2 = -log2(e)*z -> sigmoid(z)
{
    float e;
    asm("ex2.approx.f32 %0, %1;" : "=f"(e) : "f"(z2));
    float den = 1.0f + e;
    float r;
    asm("rcp.approx.f32 %0, %1;" : "=f"(r) : "f"(den));
    return r;
}

// ---------------------------------------------------------------------------
// Kernel 1: fused projection GEMM, FFMA2 inner product.
// M = 32768, K = 1024, N = 256.  BM=128, BN=64, BK=16, 8x8 per thread (as 8x4 f32x2).
// ---------------------------------------------------------------------------
__global__ __launch_bounds__(128) void proj_gemm(
    const float* __restrict__ x,
    const float* __restrict__ Wk, const float* __restrict__ Wv,
    const float* __restrict__ Wq, const float* __restrict__ Wa)
{
    __shared__ float As[16][128];   // [k][m]
    __shared__ float Bs[16][64];    // [k][c]

    const int tid = threadIdx.x;
    const int m0  = blockIdx.x * 128;
    const int c0  = blockIdx.y * 64;
    const float* W = (blockIdx.y == 0) ? Wk :
                     (blockIdx.y == 1) ? Wv :
                     (blockIdx.y == 2) ? Wq : Wa;

    const int tx = tid & 7;    // c sub-tile (0..7)
    const int ty = tid >> 3;   // m sub-tile (0..15)

    u64 acc2[8][4];
#pragma unroll
    for (int a = 0; a < 8; a++)
#pragma unroll
        for (int b = 0; b < 4; b++) acc2[a][b] = 0ull;

    const float* xrow = x + (size_t)(m0 + tid) * DIM;
    const int    brow = tid >> 1;
    const int    bcol = (tid & 1) * 8;
    const float* wrow = W + (size_t)brow * DIM + bcol;

    for (int k0 = 0; k0 < DIM; k0 += 16) {
        float4 a0 = *(const float4*)(xrow + k0);
        float4 a1 = *(const float4*)(xrow + k0 + 4);
        float4 a2 = *(const float4*)(xrow + k0 + 8);
        float4 a3 = *(const float4*)(xrow + k0 + 12);
        float4 b0 = *(const float4*)(wrow + k0);
        float4 b1 = *(const float4*)(wrow + k0 + 4);

        __syncthreads();
        As[ 0][tid] = a0.x; As[ 1][tid] = a0.y; As[ 2][tid] = a0.z; As[ 3][tid] = a0.w;
        As[ 4][tid] = a1.x; As[ 5][tid] = a1.y; As[ 6][tid] = a1.z; As[ 7][tid] = a1.w;
        As[ 8][tid] = a2.x; As[ 9][tid] = a2.y; As[10][tid] = a2.z; As[11][tid] = a2.w;
        As[12][tid] = a3.x; As[13][tid] = a3.y; As[14][tid] = a3.z; As[15][tid] = a3.w;
        Bs[bcol + 0][brow] = b0.x; Bs[bcol + 1][brow] = b0.y;
        Bs[bcol + 2][brow] = b0.z; Bs[bcol + 3][brow] = b0.w;
        Bs[bcol + 4][brow] = b1.x; Bs[bcol + 5][brow] = b1.y;
        Bs[bcol + 6][brow] = b1.z; Bs[bcol + 7][brow] = b1.w;
        __syncthreads();

#pragma unroll
        for (int k = 0; k < 16; k++) {
            float af[8];
            *(float4*)(af)     = *(const float4*)&As[k][ty * 8];
            *(float4*)(af + 4) = *(const float4*)&As[k][ty * 8 + 4];
            const u64* bp = (const u64*)&Bs[k][tx * 8];   // 32B-aligned
            u64 bv0 = bp[0], bv1 = bp[1], bv2 = bp[2], bv3 = bp[3];
#pragma unroll
            for (int im = 0; im < 8; im++) {
                u64 aa = pack2(af[im], af[im]);
                acc2[im][0] = fma2(aa, bv0, acc2[im][0]);
                acc2[im][1] = fma2(aa, bv1, acc2[im][1]);
                acc2[im][2] = fma2(aa, bv2, acc2[im][2]);
                acc2[im][3] = fma2(aa, bv3, acc2[im][3]);
            }
        }
    }

#pragma unroll
    for (int im = 0; im < 8; im++) {
        float* dst = g_P + (size_t)(m0 + ty * 8 + im) * PROJ + c0 + tx * 8;
        ulonglong2 s0; s0.x = acc2[im][0]; s0.y = acc2[im][1];
        ulonglong2 s1; s1.x = acc2[im][2]; s1.y = acc2[im][3];
        *(ulonglong2*)(dst)     = s0;
        *(ulonglong2*)(dst + 4) = s1;
    }
}

// ---------------------------------------------------------------------------
// Kernel 2: scan with one-step lookahead, f32x2-packed, load-time hoisting.
//   retrieved(t) = a(t-1)*u(t) + (1-a(t-1))*v(t-1)*wn(t)
//     u(t)  = S(t-2).k(t)       [computed at body t-1, pre-update]
//     wn(t) = k(t-1).k(t)       [computed at load time, 4-step slack]
//   out(t) = S(t).q(t) directly (off-chain, drains into later iterations)
//   S update: D = S - v*k (pre-alpha), S = alpha*D + v*k (post-alpha, 4 FFMA2)
// ---------------------------------------------------------------------------
__device__ __forceinline__ float tree8(float s, unsigned mask = 0xffffffffu)
{
    s += __shfl_xor_sync(mask, s, 1);
    s += __shfl_xor_sync(mask, s, 2);
    s += __shfl_xor_sync(mask, s, 4);
    return s;
}

__device__ __forceinline__ float dot8_tree(const u64* a, const u64* b)
{
    u64 acc = mul2(a[0], b[0]);
    acc = fma2(a[1], b[1], acc);
    acc = fma2(a[2], b[2], acc);
    acc = fma2(a[3], b[3], acc);
    float lo, hi; unpack2(lo, hi, acc);
    return tree8(lo + hi);
}

__device__ __forceinline__ void load_slot(const float* __restrict__ Pb, int t,
                                          int i, int lane8, float cb, float c1m,
                                          u64 (&k2)[4], u64 (&q2)[4],
                                          float& v, float& c0)
{
    const float* p = Pb + (size_t)t * PSTRIDE;
    const ulonglong2* kp = (const ulonglong2*)(p + lane8 * 8);
    const ulonglong2* qp = (const ulonglong2*)(p + 128 + lane8 * 8);
    ulonglong2 kv0 = kp[0], kv1 = kp[1];
    ulonglong2 qv0 = qp[0], qv1 = qp[1];
    k2[0] = kv0.x; k2[1] = kv0.y; k2[2] = kv1.x; k2[3] = kv1.y;
    q2[0] = qv0.x; q2[1] = qv0.y; q2[2] = qv1.x; q2[3] = qv1.y;
    v  = p[64 + i];
    c0 = fmaf(c1m, p[192 + i], cb);     // -log2(e)*(a + b_alpha)
}

__global__ __launch_bounds__(128, 1) void scan_kernel(
    const float* __restrict__ S0,
    const float* __restrict__ dA, const float* __restrict__ bA,
    float* __restrict__ out, float* __restrict__ Sout, int writeS)
{
    const int tid   = threadIdx.x;
    const int b     = blockIdx.x >> 2;       // batch
    const int rb    = blockIdx.x & 3;        // row block (16 rows each)
    const int rl    = tid >> 3;              // local row 0..15
    const int lane8 = tid & 7;               // column-slice within row
    const int i     = rb * 16 + rl;          // global row 0..63

    const float* Pb  = g_P + b * PROJ;
    const float c1m  = -LOG2E;
    const float cb   = -LOG2E * bA[i];
    const float c1   = -LOG2E * dA[i];
    const u64   M1   = pack2(-1.0f, -1.0f);

    u64 S2[4];
    {
        const ulonglong2* sp = (const ulonglong2*)(S0 + ((size_t)b * NDIM + i) * NDIM + lane8 * 8);
        ulonglong2 s0 = sp[0], s1 = sp[1];
        S2[0] = s0.x; S2[1] = s0.y; S2[2] = s1.x; S2[3] = s1.y;
    }

    // ring-of-4 buffers
    u64 k2[4][4], q2[4][4];
    float vb[4], c0b[4], wnb[4];
#pragma unroll
    for (int s = 0; s < 4; s++)
        load_slot(Pb, s, i, lane8, cb, c1m, k2[s], q2[s], vb[s], c0b[s]);
    wnb[0] = 0.0f;
    wnb[1] = dot8_tree(k2[0], k2[1]);
    wnb[2] = dot8_tree(k2[1], k2[2]);
    wnb[3] = dot8_tree(k2[2], k2[3]);

    // prologue: retrieved(0) = S0.k(0)
    float delta      = dot8_tree(S2, k2[0]);
    float base       = 0.0f;
    float alpha_prev = 1.0f;
    float c0cur      = c0b[0];

    float* orow = out + (size_t)b * NDIM + i;

#pragma unroll 1
    for (int t = 0; t < T_STEPS; t += 4) {
#pragma unroll
        for (int c = 0; c < 4; c++) {
            const int tt  = t + c;
            const int cn  = (c + 1) & 3;
            const int cp3 = (c + 3) & 3;
            const float vcur = vb[c];

            // ---- vk (off-chain) ----
            u64 v2 = pack2(vcur, vcur);
            u64 vk0 = mul2(v2, k2[c][0]), vk1 = mul2(v2, k2[c][1]);
            u64 vk2v = mul2(v2, k2[c][2]), vk3 = mul2(v2, k2[c][3]);

            // ---- un(t+1) accum: S(t-1).k(t+1) (pre-update S) ----
            u64 ua = mul2(S2[0], k2[cn][0]);
            ua = fma2(S2[1], k2[cn][1], ua);
            ua = fma2(S2[2], k2[cn][2], ua);
            ua = fma2(S2[3], k2[cn][3], ua);

            // ---- D = S - vk (pre-alpha) ----
            u64 D0 = fma2(vk0, M1, S2[0]);
            u64 D1 = fma2(vk1, M1, S2[1]);
            u64 D2 = fma2(vk2v, M1, S2[2]);
            u64 D3 = fma2(vk3, M1, S2[3]);

            // ---- critical chain ----
            float retrieved = fmaf(alpha_prev, delta, base);
            float z2v       = fmaf(c1, retrieved, c0cur);
            float alpha     = sigmoid_neg_l2(z2v);

            // ---- S(t) = alpha*D + vk (post-alpha: 4 FFMA2) ----
            u64 a2 = pack2(alpha, alpha);
            S2[0] = fma2(a2, D0, vk0);
            S2[1] = fma2(a2, D1, vk1);
            S2[2] = fma2(a2, D2, vk2v);
            S2[3] = fma2(a2, D3, vk3);

            // ---- un tree drains here (consumed next iteration) ----
            float ulo, uhi; unpack2(ulo, uhi, ua);
            float un = tree8(ulo + uhi);

            // ---- out(t) = S(t).q(t), fully off-chain ----
            float o = dot8_tree(S2, q2[c]);
            float res = o * o * sigmoid_neg_l2(-LOG2E * o);
            if (lane8 == 0)
                orow[(size_t)tt * (BATCH * NDIM)] = res;

            // ---- refill slot c with step tt+4; wn(t+4)=k(t+3).k(t+4) ----
            {
                int t4 = tt + 4; if (t4 > T_STEPS - 1) t4 = T_STEPS - 1;
                load_slot(Pb, t4, i, lane8, cb, c1m, k2[c], q2[c], vb[c], c0b[c]);
                wnb[c] = dot8_tree(k2[cp3], k2[c]);
            }

            // ---- carries for step t+1 ----
            base       = vcur * wnb[cn];     // v(t)*wn(t+1)
            delta      = un - base;
            alpha_prev = alpha;
            c0cur      = c0b[cn];
        }
    }

    if (writeS) {
        ulonglong2* sp = (ulonglong2*)(Sout + ((size_t)b * NDIM + i) * NDIM + lane8 * 8);
        ulonglong2 s0; s0.x = S2[0]; s0.y = S2[1];
        ulonglong2 s1; s1.x = S2[2]; s1.y = S2[3];
        sp[0] = s0; sp[1] = s1;
    }
}

// ---------------------------------------------------------------------------
extern "C" void kernel_launch(void* const* d_in, const int* in_sizes, int n_in,
                              void* d_out, int out_size)
{
    const float* x  = (const float*)d_in[0];
    const float* S0 = (const float*)d_in[1];
    const float* Wk = (const float*)d_in[2];
    const float* Wv = (const float*)d_in[3];
    const float* Wq = (const float*)d_in[4];
    const float* Wa = (const float*)d_in[5];
    const float* dA = (const float*)d_in[6];
    const float* bA = (const float*)d_in[7];

    float* out = (float*)d_out;
    const size_t out_elems = (size_t)T_STEPS * BATCH * NDIM;          // 2,097,152
    const size_t s_elems   = (size_t)BATCH * NDIM * NDIM;             //    65,536
    int writeS = ((size_t)out_size >= out_elems + s_elems) ? 1 : 0;
    float* Sout = out + out_elems;

    dim3 grid_g(T_STEPS * BATCH / 128, 4);   // (256, 4)
    proj_gemm<<<grid_g, 128>>>(x, Wk, Wv, Wq, Wa);

    scan_kernel<<<64, 128>>>(S0, dA, bA, out, Sout, writeS);
}

// round 6
// speedup vs baseline: 1.3183x; 1.3183x over previous
#include <cuda_runtime.h>
#include <cstdint>
#include <cstddef>

// Problem constants
#define T_STEPS 2048
#define BATCH   16
#define DIM     1024
#define NDIM    64
#define PROJ    256            // 4 * NDIM (k, v, q, a)
#define PSTRIDE 4096           // floats per time step = BATCH * PROJ
#define LOG2E   1.44269504f

// Scratch: projections P[(t*BATCH + b)*256 + c], c = {k:0..63, v:64..127, q:128..191, a:192..255}
__device__ float g_P[(size_t)T_STEPS * BATCH * PROJ];   // 33.5 MB

// ---------------------------------------------------------------------------
// Kernel 1: fused projection GEMM (scalar FFMA — at the fp32 roofline).
// ---------------------------------------------------------------------------
__global__ __launch_bounds__(128) void proj_gemm(
    const float* __restrict__ x,
    const float* __restrict__ Wk, const float* __restrict__ Wv,
    const float* __restrict__ Wq, const float* __restrict__ Wa)
{
    __shared__ float As[16][128];   // [k][m]
    __shared__ float Bs[16][64];    // [k][c]

    const int tid = threadIdx.x;
    const int m0  = blockIdx.x * 128;
    const int c0  = blockIdx.y * 64;
    const float* W = (blockIdx.y == 0) ? Wk :
                     (blockIdx.y == 1) ? Wv :
                     (blockIdx.y == 2) ? Wq : Wa;

    const int tx = tid & 7;    // c sub-tile (0..7)
    const int ty = tid >> 3;   // m sub-tile (0..15)

    float acc[8][8];
#pragma unroll
    for (int a = 0; a < 8; a++)
#pragma unroll
        for (int b = 0; b < 8; b++) acc[a][b] = 0.0f;

    const float* xrow = x + (size_t)(m0 + tid) * DIM;
    const int    brow = tid >> 1;
    const int    bcol = (tid & 1) * 8;
    const float* wrow = W + (size_t)brow * DIM + bcol;

    for (int k0 = 0; k0 < DIM; k0 += 16) {
        float4 a0 = *(const float4*)(xrow + k0);
        float4 a1 = *(const float4*)(xrow + k0 + 4);
        float4 a2 = *(const float4*)(xrow + k0 + 8);
        float4 a3 = *(const float4*)(xrow + k0 + 12);
        float4 b0 = *(const float4*)(wrow + k0);
        float4 b1 = *(const float4*)(wrow + k0 + 4);

        __syncthreads();
        As[ 0][tid] = a0.x; As[ 1][tid] = a0.y; As[ 2][tid] = a0.z; As[ 3][tid] = a0.w;
        As[ 4][tid] = a1.x; As[ 5][tid] = a1.y; As[ 6][tid] = a1.z; As[ 7][tid] = a1.w;
        As[ 8][tid] = a2.x; As[ 9][tid] = a2.y; As[10][tid] = a2.z; As[11][tid] = a2.w;
        As[12][tid] = a3.x; As[13][tid] = a3.y; As[14][tid] = a3.z; As[15][tid] = a3.w;
        Bs[bcol + 0][brow] = b0.x; Bs[bcol + 1][brow] = b0.y;
        Bs[bcol + 2][brow] = b0.z; Bs[bcol + 3][brow] = b0.w;
        Bs[bcol + 4][brow] = b1.x; Bs[bcol + 5][brow] = b1.y;
        Bs[bcol + 6][brow] = b1.z; Bs[bcol + 7][brow] = b1.w;
        __syncthreads();

#pragma unroll
        for (int k = 0; k < 16; k++) {
            float af[8], bf[8];
            *(float4*)(af)     = *(const float4*)&As[k][ty * 8];
            *(float4*)(af + 4) = *(const float4*)&As[k][ty * 8 + 4];
            *(float4*)(bf)     = *(const float4*)&Bs[k][tx * 8];
            *(float4*)(bf + 4) = *(const float4*)&Bs[k][tx * 8 + 4];
#pragma unroll
            for (int im = 0; im < 8; im++)
#pragma unroll
                for (int ic = 0; ic < 8; ic++)
                    acc[im][ic] = fmaf(af[im], bf[ic], acc[im][ic]);
        }
    }

#pragma unroll
    for (int im = 0; im < 8; im++) {
        float* dst = g_P + (size_t)(m0 + ty * 8 + im) * PROJ + c0 + tx * 8;
        *(float4*)(dst)     = make_float4(acc[im][0], acc[im][1], acc[im][2], acc[im][3]);
        *(float4*)(dst + 4) = make_float4(acc[im][4], acc[im][5], acc[im][6], acc[im][7]);
    }
}

// ---------------------------------------------------------------------------
// Kernel 2: scan, 16 lanes/row (4 cols each), 8 rows per 128-thr CTA,
// 128 CTAs.  TWO-step algebraic lookahead — SHFL-free carried chain:
//   retrieved(t) = a(t-1)*M(t) + (1-a(t-1))*G1(t)
//   M(t)         = a(t-2)*A(t) + (1-a(t-2))*G2(t)
//   A(t)  = S(t-3).k(t)            [3-step slack for its shuffle tree]
//   G1(t) = v(t-1)*(k(t-1).k(t))   [k.k dots at refill time, 4-step slack]
//   G2(t) = v(t-2)*(k(t-2).k(t))
//   out(t) = S(t).q(t) post-update (off-chain)
// Carried chain per step: fma -> fma -> ex2 -> add -> rcp  (~48 cy)
// ---------------------------------------------------------------------------
__device__ __forceinline__ float tree16(float s)
{
    s += __shfl_xor_sync(0xffffffffu, s, 1);
    s += __shfl_xor_sync(0xffffffffu, s, 2);
    s += __shfl_xor_sync(0xffffffffu, s, 4);
    s += __shfl_xor_sync(0xffffffffu, s, 8);
    return s;
}

__device__ __forceinline__ float dot4(const float (&a)[4], const float (&b)[4])
{
    float s0 = a[0] * b[0];
    float s1 = a[1] * b[1];
    s0 = fmaf(a[2], b[2], s0);
    s1 = fmaf(a[3], b[3], s1);
    return s0 + s1;
}

__device__ __forceinline__ float sigmoid_neg_l2(float z2)  // z2 = -log2(e)*z
{
    float e;
    asm("ex2.approx.f32 %0, %1;" : "=f"(e) : "f"(z2));
    float den = 1.0f + e;
    float r;
    asm("rcp.approx.f32 %0, %1;" : "=f"(r) : "f"(den));
    return r;
}

__device__ __forceinline__ void load_slot(const float* __restrict__ Pb, int t,
                                          int i, int lane16, float cb,
                                          float (&k)[4], float (&q)[4],
                                          float& v, float& c0)
{
    const float* p = Pb + (size_t)t * PSTRIDE;
    float4 kv = *(const float4*)(p + lane16 * 4);
    float4 qv = *(const float4*)(p + 128 + lane16 * 4);
    k[0] = kv.x; k[1] = kv.y; k[2] = kv.z; k[3] = kv.w;
    q[0] = qv.x; q[1] = qv.y; q[2] = qv.z; q[3] = qv.w;
    v  = p[64 + i];
    c0 = fmaf(-LOG2E, p[192 + i], cb);   // -log2(e)*(a + b_alpha)
}

__global__ __launch_bounds__(128, 1) void scan_kernel(
    const float* __restrict__ S0,
    const float* __restrict__ dA, const float* __restrict__ bA,
    float* __restrict__ out, float* __restrict__ Sout, int writeS)
{
    const int tid    = threadIdx.x;
    const int b      = blockIdx.x >> 3;                 // batch 0..15
    const int rb     = blockIdx.x & 7;                  // row block (8 rows)
    const int row    = tid >> 4;                        // local row 0..7
    const int lane16 = tid & 15;                        // col slice (4 cols)
    const int i      = rb * 8 + row;                    // global row 0..63

    const float* Pb = g_P + b * PROJ;
    const float cb  = -LOG2E * bA[i];
    const float c1  = -LOG2E * dA[i];

    float S[4];
    {
        float4 s = *(const float4*)(S0 + ((size_t)b * NDIM + i) * NDIM + lane16 * 4);
        S[0] = s.x; S[1] = s.y; S[2] = s.z; S[3] = s.w;
    }

    // ring-of-4 buffers
    float kb[4][4], qb[4][4], vb[4], c0b[4];
    float kk1b[4], kk2b[4], Ar[4];
#pragma unroll
    for (int s = 0; s < 4; s++)
        load_slot(Pb, s, i, lane16, cb, kb[s], qb[s], vb[s], c0b[s]);

    kk1b[0] = 0.0f;
    kk1b[1] = tree16(dot4(kb[0], kb[1]));
    kk1b[2] = tree16(dot4(kb[1], kb[2]));
    kk1b[3] = tree16(dot4(kb[2], kb[3]));
    kk2b[0] = 0.0f;
    kk2b[1] = 0.0f;
    kk2b[2] = tree16(dot4(kb[0], kb[2]));
    kk2b[3] = tree16(dot4(kb[1], kb[3]));

    Ar[0] = 0.0f;                        // A(4): written at step 1
    Ar[1] = tree16(dot4(S, kb[1]));      // A(1) = S0.k(1)
    Ar[2] = tree16(dot4(S, kb[2]));      // A(2) = S0.k(2)
    Ar[3] = 0.0f;                        // A(3): written at step 0

    // virtual history: alpha(-1)=alpha(-2)=1, v(-1)=v(-2)=0
    float alpha_prev = 1.0f;
    float vprev      = 0.0f;
    float dM         = tree16(dot4(S, kb[0]));   // M(0)-G1(0) = S0.k(0)
    float G1cur      = 0.0f;
    float c0cur      = c0b[0];

    float* orow = out + (size_t)b * NDIM + i;

#pragma unroll 1
    for (int t = 0; t < T_STEPS; t += 4) {
#pragma unroll
        for (int c = 0; c < 4; c++) {
            const int tt  = t + c;
            const int cn  = (c + 1) & 3;
            const int cp2 = (c + 2) & 3;
            const int cp3 = (c + 3) & 3;
            const float vcur = vb[c];

            // ---- off-chain: vk, D = S - vk ----
            float vk[4], D[4];
#pragma unroll
            for (int j = 0; j < 4; j++) vk[j] = vcur * kb[c][j];
#pragma unroll
            for (int j = 0; j < 4; j++) D[j] = S[j] - vk[j];

            // ---- carried chain: alpha(t) ----
            float retrieved = fmaf(alpha_prev, dM, G1cur);
            float z2        = fmaf(c1, retrieved, c0cur);
            float alpha     = sigmoid_neg_l2(z2);

            // ---- M(t+1) branch (uses alpha_prev, NOT alpha: off current chain) ----
            float G2n   = vprev * kk2b[cn];
            float Mnext = fmaf(alpha_prev, Ar[cn] - G2n, G2n);

            // ---- S(t) = alpha*D + vk ----
#pragma unroll
            for (int j = 0; j < 4; j++) S[j] = fmaf(alpha, D[j], vk[j]);

            // ---- A(t+3) = S(t).k(t+3)  (3-step slack) ----
            Ar[cp3] = tree16(dot4(S, kb[cp3]));

            // ---- out(t) = S(t).q(t), off-chain ----
            float o   = tree16(dot4(S, qb[c]));
            float res = o * o * sigmoid_neg_l2(-LOG2E * o);
            if (lane16 == 0)
                orow[(size_t)tt * (BATCH * NDIM)] = res;

            // ---- refill slot c with step tt+4; kk dots (4-step slack) ----
            {
                int t4 = tt + 4; if (t4 > T_STEPS - 1) t4 = T_STEPS - 1;
                float kn[4];
                load_slot(Pb, t4, i, lane16, cb, kn, qb[c], vb[c], c0b[c]);
                kk1b[c] = tree16(dot4(kb[cp3], kn));   // k(t+3).k(t+4)
                kk2b[c] = tree16(dot4(kb[cp2], kn));   // k(t+2).k(t+4)
#pragma unroll
                for (int j = 0; j < 4; j++) kb[c][j] = kn[j];
                int tp = tt + 16; if (tp > T_STEPS - 1) tp = T_STEPS - 1;
                const float* pf = Pb + (size_t)tp * PSTRIDE + (tid & 31) * 8;
                asm volatile("prefetch.global.L2 [%0];" :: "l"(pf));
            }

            // ---- carries for step t+1 ----
            float G1n = vcur * kk1b[cn];     // v(t)*k(t).k(t+1)
            dM        = Mnext - G1n;
            G1cur     = G1n;
            vprev     = vcur;
            alpha_prev = alpha;
            c0cur     = c0b[cn];
        }
    }

    if (writeS) {
        float* sp = Sout + ((size_t)b * NDIM + i) * NDIM + lane16 * 4;
        *(float4*)sp = make_float4(S[0], S[1], S[2], S[3]);
    }
}

// ---------------------------------------------------------------------------
extern "C" void kernel_launch(void* const* d_in, const int* in_sizes, int n_in,
                              void* d_out, int out_size)
{
    const float* x  = (const float*)d_in[0];
    const float* S0 = (const float*)d_in[1];
    const float* Wk = (const float*)d_in[2];
    const float* Wv = (const float*)d_in[3];
    const float* Wq = (const float*)d_in[4];
    const float* Wa = (const float*)d_in[5];
    const float* dA = (const float*)d_in[6];
    const float* bA = (const float*)d_in[7];

    float* out = (float*)d_out;
    const size_t out_elems = (size_t)T_STEPS * BATCH * NDIM;          // 2,097,152
    const size_t s_elems   = (size_t)BATCH * NDIM * NDIM;             //    65,536
    int writeS = ((size_t)out_size >= out_elems + s_elems) ? 1 : 0;
    float* Sout = out + out_elems;

    dim3 grid_g(T_STEPS * BATCH / 128, 4);   // (256, 4)
    proj_gemm<<<grid_g, 128>>>(x, Wk, Wv, Wq, Wa);

    scan_kernel<<<128, 128>>>(S0, dA, bA, out, Sout, writeS);
}